// round 6
// baseline (speedup 1.0000x reference)
#include <cuda_runtime.h>

// SSIM, fused single-pass box filters via per-warp sliding windows.
//
// Layout: img (16,3,512,512) f32; use channel 0 only, crop 4 -> 504x504.
// Five 11x11 zero-padded box sums computed as:
//   vertical running sums in registers (incremental add/subtract rows),
//   horizontal 11-window via log-step warp shuffles.
// Each warp: 22 output columns x 63 output rows of one image.
// 23 colgroups * 16 images * 8 strips = 2944 warps -> 736 blocks x 128 threads.

#define IMG_STRIDE (3 * 512 * 512)
#define W_IN 512
#define OUTW 504
#define CROPV 4
#define NCOLG 23          // ceil(504/22)
#define STRIPS 8
#define STRIP_H 63        // 8*63 = 504
#define NWARPS (NCOLG * 16 * STRIPS)   // 2944
#define WARPS_PER_BLOCK 4
#define NBLOCKS (NWARPS / WARPS_PER_BLOCK)  // 736

__device__ float g_partials[NWARPS];

// 11-tap sliding sum across lanes: lane L returns sum of v over lanes L..L+10.
// Valid for lanes 0..21 (needs up to lane 31).
__device__ __forceinline__ float win11(float v) {
    const unsigned m = 0xffffffffu;
    float s2 = v  + __shfl_down_sync(m, v,  1);   // 2-window
    float s4 = s2 + __shfl_down_sync(m, s2, 2);   // 4-window
    float s8 = s4 + __shfl_down_sync(m, s4, 4);   // 8-window
    float r  = s8 + __shfl_down_sync(m, s2, 8);   // 10-window
    return  r  + __shfl_down_sync(m, v, 10);      // 11-window
}

__global__ __launch_bounds__(128) void ssim_main(
    const float* __restrict__ img1, const float* __restrict__ img2)
{
    const int w    = blockIdx.x * WARPS_PER_BLOCK + (threadIdx.x >> 5);
    const int lane = threadIdx.x & 31;

    const int g     = w % NCOLG;
    const int t     = w / NCOLG;
    const int img   = t & 15;
    const int strip = t >> 4;

    // This lane's extended column in cropped coords: [22g-5, 22g+26]
    const int col   = g * 22 + lane - 5;
    const bool colok = ((unsigned)col < (unsigned)OUTW);
    const int outc  = g * 22 + lane;
    const bool outok = (lane < 22) && (outc < OUTW);

    // Base pointers with image + column folded in (col may be -5..-1; only
    // dereferenced when colok).
    const float* p1 = img1 + (long)img * IMG_STRIDE + (col + CROPV);
    const float* p2 = img2 + (long)img * IMG_STRIDE + (col + CROPV);

    const int r0 = strip * STRIP_H;
    int rmin = r0 - 5; if (rmin < 0) rmin = 0;   // first row ever added to V

    float V1 = 0.f, V2 = 0.f, V11 = 0.f, V22 = 0.f, V12 = 0.f;
    float acc = 0.f;

    const float C1 = 6.5025f;      // (0.01*255)^2
    const float C2 = 58.5225f;     // (0.03*255)^2
    const float K  = 1.0f / 121.0f;

    // Prologue: accumulate rows r0-5 .. r0+4 (zero padding for r < 0).
    #pragma unroll
    for (int k = 0; k < 10; ++k) {
        const int r = r0 - 5 + k;
        float a = 0.f, b = 0.f;
        if (r >= 0 && colok) {
            a = __ldg(p1 + (r + CROPV) * W_IN);
            b = __ldg(p2 + (r + CROPV) * W_IN);
        }
        V1 += a; V2 += b; V11 += a * a; V22 += b * b; V12 += a * b;
    }

    // Main loop over output rows.
    for (int y = r0; y < r0 + STRIP_H; ++y) {
        // Retire row y-6 (only if it was ever added; zero padding below 0).
        const int ro = y - 6;
        if (ro >= rmin) {
            float a = 0.f, b = 0.f;
            if (colok) {
                a = __ldg(p1 + (ro + CROPV) * W_IN);   // L1 hit (11-row reuse)
                b = __ldg(p2 + (ro + CROPV) * W_IN);
            }
            V1 -= a; V2 -= b; V11 -= a * a; V22 -= b * b; V12 -= a * b;
        }
        // Admit row y+5 (zero padding beyond 503).
        const int rn = y + 5;
        if (rn < OUTW) {
            float a = 0.f, b = 0.f;
            if (colok) {
                a = __ldg(p1 + (rn + CROPV) * W_IN);
                b = __ldg(p2 + (rn + CROPV) * W_IN);
            }
            V1 += a; V2 += b; V11 += a * a; V22 += b * b; V12 += a * b;
        }

        // Horizontal 11-window across lanes.
        const float B1  = win11(V1);
        const float B2  = win11(V2);
        const float B11 = win11(V11);
        const float B22 = win11(V22);
        const float B12 = win11(V12);

        if (outok) {
            const float mu1  = B1 * K;
            const float mu2  = B2 * K;
            const float mu12 = mu1 * mu2;
            const float mu1s = mu1 * mu1;
            const float mu2s = mu2 * mu2;
            const float s1  = B11 * K - mu1s;
            const float s2q = B22 * K - mu2s;
            const float s12 = B12 * K - mu12;
            const float num = (2.f * mu12 + C1) * (2.f * s12 + C2);
            const float den = (mu1s + mu2s + C1) * (s1 + s2q + C2);
            acc += __fdividef(num, den);
        }
    }

    // Warp-level reduction; one partial per warp (deterministic).
    #pragma unroll
    for (int d = 16; d; d >>= 1)
        acc += __shfl_xor_sync(0xffffffffu, acc, d);
    if (lane == 0)
        g_partials[w] = acc;
}

__global__ __launch_bounds__(256) void ssim_reduce(float* __restrict__ out)
{
    __shared__ float s[256];
    float v = 0.f;
    for (int i = threadIdx.x; i < NWARPS; i += 256)
        v += g_partials[i];
    s[threadIdx.x] = v;
    __syncthreads();
    #pragma unroll
    for (int k = 128; k > 0; k >>= 1) {
        if (threadIdx.x < k) s[threadIdx.x] += s[threadIdx.x + k];
        __syncthreads();
    }
    if (threadIdx.x == 0)
        out[0] = s[0] * (1.0f / 4064256.0f);   // 16*504*504
}

extern "C" void kernel_launch(void* const* d_in, const int* in_sizes, int n_in,
                              void* d_out, int out_size)
{
    const float* img1 = (const float*)d_in[0];
    const float* img2 = (const float*)d_in[1];
    float* out = (float*)d_out;
    ssim_main<<<NBLOCKS, 128>>>(img1, img2);
    ssim_reduce<<<1, 256>>>(out);
}

// round 7
// speedup vs baseline: 1.9009x; 1.9009x over previous
#include <cuda_runtime.h>

// SSIM, fused single-pass box filters via per-warp sliding windows.
//
// img (16,3,512,512) f32; channel 0 only, crop 4 -> 504x504 region.
// Four windowed quantities (mu1, mu2, E[x1x2], E[x1^2+x2^2]):
//   vertical 11-row running sums in registers (incremental add/retire),
//   horizontal 11-col window via log-step warp shuffles (5 SHFL each).
// Each warp: 22 output columns x 42 output rows of one image.
// 23 colgroups * 16 images * 12 strips = 4416 warps -> 1104 blocks x 128 thr
// (all CTAs co-resident: ~7.5 warps/SMSP for SHFL latency hiding).

#define IMG_STRIDE (3 * 512 * 512)
#define W_IN 512
#define OUTW 504
#define CROPV 4
#define NCOLG 23          // ceil(504/22)
#define STRIPS 12
#define STRIP_H 42        // 12*42 = 504
#define NWARPS (NCOLG * 16 * STRIPS)        // 4416
#define WARPS_PER_BLOCK 4
#define NBLOCKS (NWARPS / WARPS_PER_BLOCK)  // 1104

__device__ float g_partials[NBLOCKS];

// 11-tap sliding sum across lanes: lane L returns sum of v over lanes L..L+10.
// Valid for lanes 0..21 (consumes up to lane 31).
__device__ __forceinline__ float win11(float v) {
    const unsigned m = 0xffffffffu;
    float s2 = v  + __shfl_down_sync(m, v,  1);   // 2-window
    float s4 = s2 + __shfl_down_sync(m, s2, 2);   // 4-window
    float s8 = s4 + __shfl_down_sync(m, s4, 4);   // 8-window
    float r  = s8 + __shfl_down_sync(m, s2, 8);   // 10-window
    return  r  + __shfl_down_sync(m, v, 10);      // 11-window
}

__global__ __launch_bounds__(128) void ssim_main(
    const float* __restrict__ img1, const float* __restrict__ img2)
{
    const int wib  = threadIdx.x >> 5;
    const int w    = blockIdx.x * WARPS_PER_BLOCK + wib;
    const int lane = threadIdx.x & 31;

    const int g     = w % NCOLG;
    const int t     = w / NCOLG;
    const int img   = t & 15;
    const int strip = t >> 4;

    // This lane's extended column in cropped coords: [22g-5, 22g+26]
    const int col    = g * 22 + lane - 5;
    const bool colok = ((unsigned)col < (unsigned)OUTW);
    const int outc   = g * 22 + lane;
    const bool outok = (lane < 22) && (outc < OUTW);

    const float* p1 = img1 + (long)img * IMG_STRIDE + (col + CROPV);
    const float* p2 = img2 + (long)img * IMG_STRIDE + (col + CROPV);

    const int r0 = strip * STRIP_H;
    int rmin = r0 - 5; if (rmin < 0) rmin = 0;   // first row ever admitted

    float V1 = 0.f, V2 = 0.f, Vss = 0.f, V12 = 0.f;
    float acc = 0.f;

    const float C1 = 6.5025f;      // (0.01*255)^2
    const float C2 = 58.5225f;     // (0.03*255)^2
    const float K  = 1.0f / 121.0f;

    // Prologue: admit rows r0-5 .. r0+4 (zero padding for r < 0).
    #pragma unroll
    for (int k = 0; k < 10; ++k) {
        const int r = r0 - 5 + k;
        float a = 0.f, b = 0.f;
        if (r >= 0 && colok) {
            a = __ldg(p1 + (r + CROPV) * W_IN);
            b = __ldg(p2 + (r + CROPV) * W_IN);
        }
        V1 += a; V2 += b;
        Vss = fmaf(a, a, Vss); Vss = fmaf(b, b, Vss);
        V12 = fmaf(a, b, V12);
    }

    // Main loop over output rows.
    #pragma unroll 2
    for (int y = r0; y < r0 + STRIP_H; ++y) {
        // Retire row y-6 (only if it was ever admitted).
        const int ro = y - 6;
        if (ro >= rmin) {
            float a = 0.f, b = 0.f;
            if (colok) {
                a = __ldg(p1 + (ro + CROPV) * W_IN);   // L1 hit (11-row reuse)
                b = __ldg(p2 + (ro + CROPV) * W_IN);
            }
            V1 -= a; V2 -= b;
            Vss = fmaf(-a, a, Vss); Vss = fmaf(-b, b, Vss);
            V12 = fmaf(-a, b, V12);
        }
        // Admit row y+5 (zero padding beyond 503).
        const int rn = y + 5;
        if (rn < OUTW) {
            float a = 0.f, b = 0.f;
            if (colok) {
                a = __ldg(p1 + (rn + CROPV) * W_IN);
                b = __ldg(p2 + (rn + CROPV) * W_IN);
            }
            V1 += a; V2 += b;
            Vss = fmaf(a, a, Vss); Vss = fmaf(b, b, Vss);
            V12 = fmaf(a, b, V12);
        }

        // Horizontal 11-window across lanes (4 independent shfl chains).
        const float B1  = win11(V1);
        const float B2  = win11(V2);
        const float Bss = win11(Vss);
        const float B12 = win11(V12);

        if (outok) {
            const float mu1  = B1 * K;
            const float mu2  = B2 * K;
            const float mu12 = mu1 * mu2;
            const float musq = fmaf(mu1, mu1, mu2 * mu2);
            const float s12  = fmaf(B12, K, -mu12);   // sigma12
            const float sss  = fmaf(Bss, K, -musq);   // sigma1^2 + sigma2^2
            const float num  = fmaf(2.f, mu12, C1) * fmaf(2.f, s12, C2);
            const float den  = (musq + C1) * (sss + C2);
            acc += __fdividef(num, den);
        }
    }

    // Warp-level reduction, then block-level partial (deterministic).
    #pragma unroll
    for (int d = 16; d; d >>= 1)
        acc += __shfl_xor_sync(0xffffffffu, acc, d);

    __shared__ float sp[WARPS_PER_BLOCK];
    if (lane == 0) sp[wib] = acc;
    __syncthreads();
    if (threadIdx.x == 0) {
        float s = sp[0];
        #pragma unroll
        for (int i = 1; i < WARPS_PER_BLOCK; ++i) s += sp[i];
        g_partials[blockIdx.x] = s;
    }
}

__global__ __launch_bounds__(1024) void ssim_reduce(float* __restrict__ out)
{
    const int tid = threadIdx.x;
    float v = 0.f;
    if (tid < NBLOCKS)        v  = g_partials[tid];
    if (tid + 1024 < NBLOCKS) v += g_partials[tid + 1024];

    #pragma unroll
    for (int d = 16; d; d >>= 1)
        v += __shfl_xor_sync(0xffffffffu, v, d);

    __shared__ float s[32];
    if ((tid & 31) == 0) s[tid >> 5] = v;
    __syncthreads();
    if (tid < 32) {
        float x = s[tid];
        #pragma unroll
        for (int d = 16; d; d >>= 1)
            x += __shfl_xor_sync(0xffffffffu, x, d);
        if (tid == 0)
            out[0] = x * (1.0f / 4064256.0f);   // 16*504*504
    }
}

extern "C" void kernel_launch(void* const* d_in, const int* in_sizes, int n_in,
                              void* d_out, int out_size)
{
    const float* img1 = (const float*)d_in[0];
    const float* img2 = (const float*)d_in[1];
    float* out = (float*)d_out;
    ssim_main<<<NBLOCKS, 128>>>(img1, img2);
    ssim_reduce<<<1, 1024>>>(out);
}